// round 13
// baseline (speedup 1.0000x reference)
#include <cuda_runtime.h>

// OMul: r[i] = outer(x[i], y[i]) flattened.
// x: [N, 256] f32, y: [N, 256] f32, out: [N, 65536] f32.
// Pure HBM-write-bound: 1 GiB of output stores.
//
// R12: exact R9 champion (grid=4096, 1 row/CTA, smem-staged inputs,
// warp-uniform LDS broadcast, fully unrolled, 512B contiguous per warp per
// iteration) with ONE change: __stwt (st.global.wt) write-through stores
// instead of __stcs. A/B on the final cache-op axis point:
//   .wb = 61% DRAM (L2 thrash), .cs = 83% (evict-first), .wt = ? (no L2
//   dirty-line lifecycle at all; stores pushed toward DRAM at store time).

static constexpr int M = 256;
static constexpr int K = 256;
static constexpr int THREADS = 256;

__global__ __launch_bounds__(THREADS, 8)
void omul_kernel(const float* __restrict__ x,
                 const float* __restrict__ y,
                 float* __restrict__ out)
{
    __shared__ float sx[M];
    __shared__ float sy[K];

    const int row = blockIdx.x;
    const int t   = threadIdx.x;

    sx[t] = x[(size_t)row * M + t];
    sy[t] = y[(size_t)row * K + t];
    __syncthreads();

    const int k4 = t & 63;        // which float4 chunk of k (0..63)
    const int m0 = t >> 6;        // 0..3: m offset within group of 4

    const float4 y4 = reinterpret_cast<const float4*>(sy)[k4];

    float4* out4 = reinterpret_cast<float4*>(out + (size_t)row * (M * K));

    #pragma unroll
    for (int mi = 0; mi < 64; mi++) {
        const int m = m0 + mi * 4;
        const float xv = sx[m];     // warp-uniform broadcast
        float4 v;
        v.x = xv * y4.x;
        v.y = xv * y4.y;
        v.z = xv * y4.z;
        v.w = xv * y4.w;
        // write-through streaming store: no L2 dirty-line lifecycle
        __stwt(&out4[(size_t)m * 64 + k4], v);
    }
}

extern "C" void kernel_launch(void* const* d_in, const int* in_sizes, int n_in,
                              void* d_out, int out_size)
{
    const float* x = (const float*)d_in[0];
    const float* y = (const float*)d_in[1];
    float* out = (float*)d_out;

    const int n = in_sizes[0] / M;   // 4096 rows

    omul_kernel<<<n, THREADS>>>(x, y, out);
}

// round 14
// speedup vs baseline: 1.0313x; 1.0313x over previous
#include <cuda_runtime.h>

// OMul: r[i] = outer(x[i], y[i]) flattened.
// x: [N, 256] f32, y: [N, 256] f32, out: [N, 65536] f32.
// Pure HBM-write-bound: 1 GiB of .cs streaming stores.
//
// R14: R9 champion store stream (grid=4096, 1 row/CTA, smem-staged,
// warp-uniform LDS broadcast, full unroll, __stcs float4, 512B/warp/iter)
// with 512-thread CTAs: same 2048 threads/SM (occ 4x512 vs 8x256) but half
// the per-SM prologue/barrier instances and coarser wave structure.
// Thread t: k4 = t & 63, m0 = t >> 6 (0..7); 32 stores per thread.

static constexpr int M = 256;
static constexpr int K = 256;
static constexpr int THREADS = 512;

__global__ __launch_bounds__(THREADS, 4)
void omul_kernel(const float* __restrict__ x,
                 const float* __restrict__ y,
                 float* __restrict__ out)
{
    __shared__ float sx[M];
    __shared__ float sy[K];

    const int row = blockIdx.x;
    const int t   = threadIdx.x;

    if (t < M) {
        sx[t] = x[(size_t)row * M + t];
        sy[t] = y[(size_t)row * K + t];
    }
    __syncthreads();

    const int k4 = t & 63;        // which float4 chunk of k (0..63)
    const int m0 = t >> 6;        // 0..7: m offset within group of 8

    const float4 y4 = reinterpret_cast<const float4*>(sy)[k4];

    float4* out4 = reinterpret_cast<float4*>(out + (size_t)row * (M * K));

    #pragma unroll
    for (int mi = 0; mi < 32; mi++) {
        const int m = m0 + mi * 8;
        const float xv = sx[m];     // warp-uniform broadcast
        float4 v;
        v.x = xv * y4.x;
        v.y = xv * y4.y;
        v.z = xv * y4.z;
        v.w = xv * y4.w;
        // streaming store: output never re-read, full 128B sector coverage
        __stcs(&out4[(size_t)m * 64 + k4], v);
    }
}

extern "C" void kernel_launch(void* const* d_in, const int* in_sizes, int n_in,
                              void* d_out, int out_size)
{
    const float* x = (const float*)d_in[0];
    const float* y = (const float*)d_in[1];
    float* out = (float*)d_out;

    const int n = in_sizes[0] / M;   // 4096 rows

    omul_kernel<<<n, THREADS>>>(x, y, out);
}

// round 16
// speedup vs baseline: 1.0614x; 1.0292x over previous
#include <cuda_runtime.h>

// OMul: r[i] = outer(x[i], y[i]) flattened.
// x: [N, 256] f32, y: [N, 256] f32, out: [N, 65536] f32.
// Pure HBM-write-bound: 1 GiB of .cs streaming stores.
//
// R15: continue the R14 winning axis (fewer, larger CTAs; per-SM prologue
// count 8 -> 4 -> 2): 1024-thread CTAs, 1 row/CTA, grid=4096.
// Thread t: k4 = t & 63, m0 = t >> 6 (0..15); 16 stores per thread.
// Store stream byte-identical per warp: 512B contiguous, warp-uniform xv,
// full unroll, __stcs.

static constexpr int M = 256;
static constexpr int K = 256;
static constexpr int THREADS = 1024;

__global__ __launch_bounds__(THREADS, 2)
void omul_kernel(const float* __restrict__ x,
                 const float* __restrict__ y,
                 float* __restrict__ out)
{
    __shared__ float sx[M];
    __shared__ float sy[K];

    const int row = blockIdx.x;
    const int t   = threadIdx.x;

    if (t < M) {
        sx[t] = x[(size_t)row * M + t];
        sy[t] = y[(size_t)row * K + t];
    }
    __syncthreads();

    const int k4 = t & 63;        // which float4 chunk of k (0..63)
    const int m0 = t >> 6;        // 0..15: m offset within group of 16

    const float4 y4 = reinterpret_cast<const float4*>(sy)[k4];

    float4* out4 = reinterpret_cast<float4*>(out + (size_t)row * (M * K));

    #pragma unroll
    for (int mi = 0; mi < 16; mi++) {
        const int m = m0 + mi * 16;
        const float xv = sx[m];     // warp-uniform broadcast
        float4 v;
        v.x = xv * y4.x;
        v.y = xv * y4.y;
        v.z = xv * y4.z;
        v.w = xv * y4.w;
        // streaming store: output never re-read, full 128B sector coverage
        __stcs(&out4[(size_t)m * 64 + k4], v);
    }
}

extern "C" void kernel_launch(void* const* d_in, const int* in_sizes, int n_in,
                              void* d_out, int out_size)
{
    const float* x = (const float*)d_in[0];
    const float* y = (const float*)d_in[1];
    float* out = (float*)d_out;

    const int n = in_sizes[0] / M;   // 4096 rows

    omul_kernel<<<n, THREADS>>>(x, y, out);
}